// round 9
// baseline (speedup 1.0000x reference)
#include <cuda_runtime.h>

// ---------------------------------------------------------------------------
// C3 sparsely-connected 5x5 conv, fp32, FFMA2 (fma.rn.f32x2) path, sm_103a.
// x: [32,6,512,512], w: [16,6,5,5], bias: [16] -> out: [32,16,508,508]
//
// R9: shared-memory wavefront diet (R8 was L1TEX-bound at 96%).
//  - 3 CTAs/SM, 64x8 tile, 4 px x 8 co per thread (acc = 32 regs).
//  - Single aligned input copy; odd pairs built with register packs.
//  - Weights staged in consumption-order streams per (half, ci, ky);
//    consumed two output channels at a time: 5 aligned LDS.128 per 2 co.
// ---------------------------------------------------------------------------

#define IN_H 512
#define IN_W 512
#define OUT_H 508
#define OUT_W 508
#define N_CI 6
#define N_CO 16

#define TILE_W 64
#define TILE_H 8
#define IN_TH 12          // TILE_H + 4
#define SA_STRIDE 68      // row stride in floats (272B, 16B-aligned rows)
#define CI_TILE (IN_TH * SA_STRIDE)   // 816 floats per channel plane
#define NTHREADS 256

#define SW_U64   1560                            // total weight pairs incl pad
#define SW_BYTES (SW_U64 * 8)                    // 12480
#define SA_BYTES (N_CI * CI_TILE * 4)            // 19584
#define SMEM_BYTES (SW_BYTES + SA_BYTES)         // 32064

typedef unsigned long long u64;

// Balanced co partition: 30 connected (co,ci) pairs per half.
__device__ constexpr int H_CO[2][8] = {
    {0, 1, 2, 3, 6, 7, 8, 15},
    {4, 5, 9, 10, 11, 12, 13, 14},
};
__device__ constexpr int HCNT[2][6] = { {3, 5, 7, 7, 5, 3}, {7, 5, 3, 3, 5, 7} };
__device__ constexpr int HLST[2][6][7] = {
  { // half 0
    {0, 4, 7, 0, 0, 0, 0},
    {0, 1, 4, 5, 7, 0, 0},
    {0, 1, 2, 4, 5, 6, 7},
    {1, 2, 3, 4, 5, 6, 7},
    {2, 3, 5, 6, 7, 0, 0},
    {3, 6, 7, 0, 0, 0, 0},
  },
  { // half 1
    {0, 1, 2, 3, 4, 5, 7},
    {1, 3, 4, 5, 6, 0, 0},
    {4, 6, 7, 0, 0, 0, 0},
    {2, 5, 7, 0, 0, 0, 0},
    {0, 2, 3, 5, 6, 0, 0},
    {0, 1, 2, 3, 4, 6, 7},
  },
};
// Weight stream geometry (u64 units). Stream (h,ci,ky) holds HCNT*5 pairs in
// consumption order (co-major, kx minor), padded to even count (16B align).
__device__ constexpr int PSZ[2][6]  = { {16, 26, 36, 36, 26, 16},
                                        {36, 26, 16, 16, 26, 36} };
__device__ constexpr int WOFF[2][6] = { {0, 80, 210, 390, 570, 700},
                                        {780, 960, 1090, 1170, 1250, 1380} };
// Cumulative real-pair counts per ci for staging decode.
__device__ constexpr int CUMP[2][7] = { {0, 75, 200, 375, 550, 675, 750},
                                        {0, 175, 300, 375, 450, 575, 750} };

__device__ __forceinline__ u64 pk2(float lo, float hi) {
    u64 r;
    asm("mov.b64 %0, {%1, %2};" : "=l"(r) : "f"(lo), "f"(hi));
    return r;
}

__device__ __forceinline__ void fma2(u64& d, u64 a, u64 b) {
    asm("fma.rn.f32x2 %0, %1, %2, %0;" : "+l"(d) : "l"(a), "l"(b));
}

__device__ __forceinline__ float2 upk(u64 v) {
    float2 r;
    asm("mov.b64 {%0, %1}, %2;" : "=f"(r.x), "=f"(r.y) : "l"(v));
    return r;
}

// One output channel's 5 kx taps against the 7 input pairs.
__device__ __forceinline__ void conv5(u64* acc2, const u64* pe, const u64* po,
                                      u64 w0, u64 w1, u64 w2, u64 w3, u64 w4) {
    fma2(acc2[0], pe[0], w0);  fma2(acc2[1], pe[1], w0);   // kx=0
    fma2(acc2[0], po[0], w1);  fma2(acc2[1], po[1], w1);   // kx=1
    fma2(acc2[0], pe[1], w2);  fma2(acc2[1], pe[2], w2);   // kx=2
    fma2(acc2[0], po[1], w3);  fma2(acc2[1], po[2], w3);   // kx=3
    fma2(acc2[0], pe[2], w4);  fma2(acc2[1], pe[3], w4);   // kx=4
}

template <int H>
__device__ __forceinline__ void compute_half(
    const float* __restrict__ sA, const u64* __restrict__ sW,
    const float* __restrict__ bias, float* __restrict__ out,
    int b, int x0, int y0, int txi, int row)
{
    u64 acc[8][2];
#pragma unroll
    for (int a = 0; a < 8; ++a) {
        float bv = __ldg(bias + H_CO[H][a]);
        u64 bb = pk2(bv, bv);
        acc[a][0] = bb; acc[a][1] = bb;
    }

#pragma unroll
    for (int ci = 0; ci < N_CI; ++ci) {
        const float* bA = sA + ci * CI_TILE + row * SA_STRIDE + txi;
        const int psz = PSZ[H][ci];
        const int cnt = HCNT[H][ci];
#pragma unroll 1
        for (int ky = 0; ky < 5; ++ky) {
            // input row: 8 floats via 2x aligned LDS.128
            float4 fa = *reinterpret_cast<const float4*>(bA + ky * SA_STRIDE);
            float4 fc = *reinterpret_cast<const float4*>(bA + ky * SA_STRIDE + 4);
            u64 pe[4], po[3];
            pe[0] = pk2(fa.x, fa.y);   // natural pairs: no MOVs
            pe[1] = pk2(fa.z, fa.w);
            pe[2] = pk2(fc.x, fc.y);
            pe[3] = pk2(fc.z, fc.w);
            po[0] = pk2(fa.y, fa.z);   // cross pairs: 2 MOVs each
            po[1] = pk2(fa.w, fc.x);
            po[2] = pk2(fc.y, fc.z);

            const ulonglong2* wv2 = reinterpret_cast<const ulonglong2*>(
                sW + WOFF[H][ci] + ky * psz);

            // two output channels per 5 aligned LDS.128 (10 weight pairs)
#pragma unroll
            for (int u = 0; u < cnt / 2; ++u) {
                ulonglong2 W0 = wv2[5 * u + 0];
                ulonglong2 W1 = wv2[5 * u + 1];
                ulonglong2 W2 = wv2[5 * u + 2];
                ulonglong2 W3 = wv2[5 * u + 3];
                ulonglong2 W4 = wv2[5 * u + 4];
                const int a0 = HLST[H][ci][2 * u];
                const int a1 = HLST[H][ci][2 * u + 1];
                conv5(acc[a0], pe, po, W0.x, W0.y, W1.x, W1.y, W2.x);
                conv5(acc[a1], pe, po, W2.y, W3.x, W3.y, W4.x, W4.y);
            }
            {   // tail channel (cnt is odd): pairs [5t, 5t+4], t even
                const int t = cnt - 1;
                ulonglong2 T0 = wv2[(5 * t) / 2];
                ulonglong2 T1 = wv2[(5 * t) / 2 + 1];
                u64 t4 = reinterpret_cast<const u64*>(wv2)[5 * t + 4];
                const int a0 = HLST[H][ci][t];
                conv5(acc[a0], pe, po, T0.x, T0.y, T1.x, T1.y, t4);
            }
        }
    }

    const int ox = x0 + txi;
    const int oy = y0 + row;
    if (ox < OUT_W && oy < OUT_H) {
        float* ob = out + (size_t)b * (N_CO * OUT_H * OUT_W)
                        + (size_t)oy * OUT_W + ox;
#pragma unroll
        for (int a = 0; a < 8; ++a) {
            float2 v0 = upk(acc[a][0]);
            float2 v1 = upk(acc[a][1]);
            *reinterpret_cast<float4*>(ob + (size_t)H_CO[H][a] * (OUT_H * OUT_W)) =
                make_float4(v0.x, v0.y, v1.x, v1.y);
        }
    }
}

__global__ __launch_bounds__(NTHREADS, 3)
void c3_kernel(const float* __restrict__ x,
               const float* __restrict__ w,
               const float* __restrict__ bias,
               float* __restrict__ out) {
    extern __shared__ unsigned char smem[];
    u64*   sW = reinterpret_cast<u64*>(smem);
    float* sA = reinterpret_cast<float*>(smem + SW_BYTES);

    const int tid = threadIdx.x;
    const int b   = blockIdx.z;
    const int x0  = blockIdx.x * TILE_W;
    const int y0  = blockIdx.y * TILE_H;

    // --- stage weights into consumption-order streams -----------------------
    // item space: [h:2][real pairs of that half:750] -> (ci,t,ky,kx)
    for (int idx = tid; idx < 1500; idx += NTHREADS) {
        int h = idx / 750;
        int r = idx - h * 750;
        int ci = 0;
#pragma unroll
        for (int c = 0; c < 5; ++c) ci += (r >= CUMP[h][c + 1]);
        int q  = r - CUMP[h][ci];
        int t  = q / 25;
        int rm = q - t * 25;
        int ky = rm / 5;
        int kx = rm - ky * 5;
        int co = H_CO[h][HLST[h][ci][t]];
        float wv = w[co * 150 + ci * 25 + ky * 5 + kx];
        sW[WOFF[h][ci] + ky * PSZ[h][ci] + t * 5 + kx] = pk2(wv, wv);
    }

    // --- stage input tile (single aligned copy) -----------------------------
    const float* xb = x + (size_t)b * (N_CI * IN_H * IN_W);
    for (int i = tid; i < N_CI * IN_TH * 17; i += NTHREADS) {
        int ci  = i / (IN_TH * 17);
        int rem = i - ci * (IN_TH * 17);
        int r   = rem / 17;
        int c4  = (rem - r * 17) * 4;
        int gy  = y0 + r;
        int gx  = x0 + c4;
        float4 v = make_float4(0.f, 0.f, 0.f, 0.f);
        if (gy < IN_H && gx < IN_W) {
            v = *reinterpret_cast<const float4*>(
                    xb + (size_t)ci * (IN_H * IN_W) + (size_t)gy * IN_W + gx);
        }
        *reinterpret_cast<float4*>(sA + ci * CI_TILE + r * SA_STRIDE + c4) = v;
    }
    __syncthreads();

    const int xg   = tid & 15;         // 16 x-groups of 4 px
    const int row  = (tid >> 4) & 7;   // 8 rows
    const int half = tid >> 7;         // channel half (uniform per warp)
    const int txi  = xg * 4;

    if (half == 0)
        compute_half<0>(sA, sW, bias, out, b, x0, y0, txi, row);
    else
        compute_half<1>(sA, sW, bias, out, b, x0, y0, txi, row);
}

extern "C" void kernel_launch(void* const* d_in, const int* in_sizes, int n_in,
                              void* d_out, int out_size) {
    const float* x    = (const float*)d_in[0];   // [32,6,512,512]
    const float* w    = (const float*)d_in[1];   // [16,6,5,5]
    const float* bias = (const float*)d_in[2];   // [16]
    float* out = (float*)d_out;                  // [32,16,508,508]

    cudaFuncSetAttribute(c3_kernel,
                         cudaFuncAttributeMaxDynamicSharedMemorySize,
                         SMEM_BYTES);

    dim3 grid((OUT_W + TILE_W - 1) / TILE_W,    // 8
              (OUT_H + TILE_H - 1) / TILE_H,    // 64
              32);                              // batch
    c3_kernel<<<grid, NTHREADS, SMEM_BYTES>>>(x, w, bias, out);
}

// round 10
// speedup vs baseline: 1.1065x; 1.1065x over previous
#include <cuda_runtime.h>

// ---------------------------------------------------------------------------
// C3 sparsely-connected 5x5 conv, fp32, FFMA2 (fma.rn.f32x2) path, sm_103a.
// x: [32,6,512,512], w: [16,6,5,5], bias: [16] -> out: [32,16,508,508]
//
// R10 = R8's input path (dual smem copy, operands straight from LDS, zero
// register packs) + R9's weight path (consumption-order streams, two output
// channels per 5 aligned LDS.128).
//  - 3 CTAs/SM (launch_bounds(256,3)), 64x8 tile, 4 px x 8 co per thread.
//  - Input stride 68 floats; aligned copy + 1-float-shifted copy.
// ---------------------------------------------------------------------------

#define IN_H 512
#define IN_W 512
#define OUT_H 508
#define OUT_W 508
#define N_CI 6
#define N_CO 16

#define TILE_W 64
#define TILE_H 8
#define IN_TH 12          // TILE_H + 4
#define SA_STRIDE 68      // row stride in floats (272B, 16B-aligned rows)
#define CI_TILE (IN_TH * SA_STRIDE)   // 816 floats per channel plane
#define NTHREADS 256

#define SW_U64   1560                            // weight pairs incl padding
#define SW_BYTES (SW_U64 * 8)                    // 12480
#define SA_BYTES (N_CI * CI_TILE * 4)            // 19584
#define SMEM_BYTES (SW_BYTES + 2 * SA_BYTES)     // 51648

typedef unsigned long long u64;

// Balanced co partition: 30 connected (co,ci) pairs per half.
__device__ constexpr int H_CO[2][8] = {
    {0, 1, 2, 3, 6, 7, 8, 15},
    {4, 5, 9, 10, 11, 12, 13, 14},
};
__device__ constexpr int HCNT[2][6] = { {3, 5, 7, 7, 5, 3}, {7, 5, 3, 3, 5, 7} };
__device__ constexpr int HLST[2][6][7] = {
  { // half 0
    {0, 4, 7, 0, 0, 0, 0},
    {0, 1, 4, 5, 7, 0, 0},
    {0, 1, 2, 4, 5, 6, 7},
    {1, 2, 3, 4, 5, 6, 7},
    {2, 3, 5, 6, 7, 0, 0},
    {3, 6, 7, 0, 0, 0, 0},
  },
  { // half 1
    {0, 1, 2, 3, 4, 5, 7},
    {1, 3, 4, 5, 6, 0, 0},
    {4, 6, 7, 0, 0, 0, 0},
    {2, 5, 7, 0, 0, 0, 0},
    {0, 2, 3, 5, 6, 0, 0},
    {0, 1, 2, 3, 4, 6, 7},
  },
};
// Weight stream geometry (u64 units). Stream (h,ci,ky) holds HCNT*5 pairs in
// consumption order (co-major, kx minor), padded to even count (16B align).
__device__ constexpr int PSZ[2][6]  = { {16, 26, 36, 36, 26, 16},
                                        {36, 26, 16, 16, 26, 36} };
__device__ constexpr int WOFF[2][6] = { {0, 80, 210, 390, 570, 700},
                                        {780, 960, 1090, 1170, 1250, 1380} };
// Cumulative real-pair counts per ci for staging decode.
__device__ constexpr int CUMP[2][7] = { {0, 75, 200, 375, 550, 675, 750},
                                        {0, 175, 300, 375, 450, 575, 750} };

__device__ __forceinline__ u64 pk2(float lo, float hi) {
    u64 r;
    asm("mov.b64 %0, {%1, %2};" : "=l"(r) : "f"(lo), "f"(hi));
    return r;
}

__device__ __forceinline__ void fma2(u64& d, u64 a, u64 b) {
    asm("fma.rn.f32x2 %0, %1, %2, %0;" : "+l"(d) : "l"(a), "l"(b));
}

__device__ __forceinline__ float2 upk(u64 v) {
    float2 r;
    asm("mov.b64 {%0, %1}, %2;" : "=f"(r.x), "=f"(r.y) : "l"(v));
    return r;
}

// One output channel's 5 kx taps against the 7 input pairs.
__device__ __forceinline__ void conv5(u64* acc2, const u64* pe, const u64* po,
                                      u64 w0, u64 w1, u64 w2, u64 w3, u64 w4) {
    fma2(acc2[0], pe[0], w0);  fma2(acc2[1], pe[1], w0);   // kx=0
    fma2(acc2[0], po[0], w1);  fma2(acc2[1], po[1], w1);   // kx=1
    fma2(acc2[0], pe[1], w2);  fma2(acc2[1], pe[2], w2);   // kx=2
    fma2(acc2[0], po[1], w3);  fma2(acc2[1], po[2], w3);   // kx=3
    fma2(acc2[0], pe[2], w4);  fma2(acc2[1], pe[3], w4);   // kx=4
}

template <int H>
__device__ __forceinline__ void compute_half(
    const float* __restrict__ sA, const float* __restrict__ sB,
    const u64* __restrict__ sW, const float* __restrict__ bias,
    float* __restrict__ out, int b, int x0, int y0, int txi, int row)
{
    u64 acc[8][2];
#pragma unroll
    for (int a = 0; a < 8; ++a) {
        float bv = __ldg(bias + H_CO[H][a]);
        u64 bb = pk2(bv, bv);
        acc[a][0] = bb; acc[a][1] = bb;
    }

#pragma unroll
    for (int ci = 0; ci < N_CI; ++ci) {
        const float* bA = sA + ci * CI_TILE + row * SA_STRIDE + txi;
        const float* bB = sB + ci * CI_TILE + row * SA_STRIDE + txi;
        const int psz = PSZ[H][ci];
        const int cnt = HCNT[H][ci];
#pragma unroll 1
        for (int ky = 0; ky < 5; ++ky) {
            // input pairs straight from LDS: no register packing
            // even pairs j=0,2,4,6 from aligned copy: 2x LDS.128
            ulonglong2 e0 = *reinterpret_cast<const ulonglong2*>(bA + ky * SA_STRIDE);
            ulonglong2 e1 = *reinterpret_cast<const ulonglong2*>(bA + ky * SA_STRIDE + 4);
            // odd pairs j=1,3 from shifted copy: LDS.128; j=5: LDS.64
            ulonglong2 o0 = *reinterpret_cast<const ulonglong2*>(bB + ky * SA_STRIDE);
            u64        o2 = *reinterpret_cast<const u64*>(bB + ky * SA_STRIDE + 4);
            u64 pe[4] = {e0.x, e0.y, e1.x, e1.y};   // j = 0,2,4,6
            u64 po[3] = {o0.x, o0.y, o2};           // j = 1,3,5

            const ulonglong2* wv2 = reinterpret_cast<const ulonglong2*>(
                sW + WOFF[H][ci] + ky * psz);

            // two output channels per 5 aligned LDS.128 (10 weight pairs)
#pragma unroll
            for (int u = 0; u < cnt / 2; ++u) {
                ulonglong2 W0 = wv2[5 * u + 0];
                ulonglong2 W1 = wv2[5 * u + 1];
                ulonglong2 W2 = wv2[5 * u + 2];
                ulonglong2 W3 = wv2[5 * u + 3];
                ulonglong2 W4 = wv2[5 * u + 4];
                const int a0 = HLST[H][ci][2 * u];
                const int a1 = HLST[H][ci][2 * u + 1];
                conv5(acc[a0], pe, po, W0.x, W0.y, W1.x, W1.y, W2.x);
                conv5(acc[a1], pe, po, W2.y, W3.x, W3.y, W4.x, W4.y);
            }
            {   // tail channel (cnt odd): pairs [5t, 5t+4], t even
                const int t = cnt - 1;
                ulonglong2 T0 = wv2[(5 * t) / 2];
                ulonglong2 T1 = wv2[(5 * t) / 2 + 1];
                u64 t4 = reinterpret_cast<const u64*>(wv2)[5 * t + 4];
                const int a0 = HLST[H][ci][t];
                conv5(acc[a0], pe, po, T0.x, T0.y, T1.x, T1.y, t4);
            }
        }
    }

    const int ox = x0 + txi;
    const int oy = y0 + row;
    if (ox < OUT_W && oy < OUT_H) {
        float* ob = out + (size_t)b * (N_CO * OUT_H * OUT_W)
                        + (size_t)oy * OUT_W + ox;
#pragma unroll
        for (int a = 0; a < 8; ++a) {
            float2 v0 = upk(acc[a][0]);
            float2 v1 = upk(acc[a][1]);
            *reinterpret_cast<float4*>(ob + (size_t)H_CO[H][a] * (OUT_H * OUT_W)) =
                make_float4(v0.x, v0.y, v1.x, v1.y);
        }
    }
}

__global__ __launch_bounds__(NTHREADS, 3)
void c3_kernel(const float* __restrict__ x,
               const float* __restrict__ w,
               const float* __restrict__ bias,
               float* __restrict__ out) {
    extern __shared__ unsigned char smem[];
    u64*   sW = reinterpret_cast<u64*>(smem);
    float* sA = reinterpret_cast<float*>(smem + SW_BYTES);
    float* sB = reinterpret_cast<float*>(smem + SW_BYTES + SA_BYTES);

    const int tid = threadIdx.x;
    const int b   = blockIdx.z;
    const int x0  = blockIdx.x * TILE_W;
    const int y0  = blockIdx.y * TILE_H;

    // --- stage weights into consumption-order streams -----------------------
    for (int idx = tid; idx < 1500; idx += NTHREADS) {
        int h = idx / 750;
        int r = idx - h * 750;
        int ci = 0;
#pragma unroll
        for (int c = 0; c < 5; ++c) ci += (r >= CUMP[h][c + 1]);
        int q  = r - CUMP[h][ci];
        int t  = q / 25;
        int rm = q - t * 25;
        int ky = rm / 5;
        int kx = rm - ky * 5;
        int co = H_CO[h][HLST[h][ci][t]];
        float wv = w[co * 150 + ci * 25 + ky * 5 + kx];
        sW[WOFF[h][ci] + ky * PSZ[h][ci] + t * 5 + kx] = pk2(wv, wv);
    }

    // --- stage input tile into BOTH copies (aligned + shifted by 1 float) --
    const float* xb = x + (size_t)b * (N_CI * IN_H * IN_W);
    for (int i = tid; i < N_CI * IN_TH * 17; i += NTHREADS) {
        int ci  = i / (IN_TH * 17);
        int rem = i - ci * (IN_TH * 17);
        int r   = rem / 17;
        int c4  = (rem - r * 17) * 4;
        int gy  = y0 + r;
        int gx  = x0 + c4;
        float4 v = make_float4(0.f, 0.f, 0.f, 0.f);
        if (gy < IN_H && gx < IN_W) {
            v = *reinterpret_cast<const float4*>(
                    xb + (size_t)ci * (IN_H * IN_W) + (size_t)gy * IN_W + gx);
        }
        float* dA = sA + ci * CI_TILE + r * SA_STRIDE + c4;
        *reinterpret_cast<float4*>(dA) = v;
        // shifted copy: B[c] = in[c+1]
        float* dB = sB + ci * CI_TILE + r * SA_STRIDE + c4;
        if (c4 > 0) dB[-1] = v.x;
        dB[0] = v.y; dB[1] = v.z; dB[2] = v.w;
    }
    __syncthreads();

    const int xg   = tid & 15;         // 16 x-groups of 4 px
    const int row  = (tid >> 4) & 7;   // 8 rows
    const int half = tid >> 7;         // channel half (uniform per warp)
    const int txi  = xg * 4;

    if (half == 0)
        compute_half<0>(sA, sB, sW, bias, out, b, x0, y0, txi, row);
    else
        compute_half<1>(sA, sB, sW, bias, out, b, x0, y0, txi, row);
}

extern "C" void kernel_launch(void* const* d_in, const int* in_sizes, int n_in,
                              void* d_out, int out_size) {
    const float* x    = (const float*)d_in[0];   // [32,6,512,512]
    const float* w    = (const float*)d_in[1];   // [16,6,5,5]
    const float* bias = (const float*)d_in[2];   // [16]
    float* out = (float*)d_out;                  // [32,16,508,508]

    cudaFuncSetAttribute(c3_kernel,
                         cudaFuncAttributeMaxDynamicSharedMemorySize,
                         SMEM_BYTES);

    dim3 grid((OUT_W + TILE_W - 1) / TILE_W,    // 8
              (OUT_H + TILE_H - 1) / TILE_H,    // 64
              32);                              // batch
    c3_kernel<<<grid, NTHREADS, SMEM_BYTES>>>(x, w, bias, out);
}

// round 11
// speedup vs baseline: 1.2855x; 1.1618x over previous
#include <cuda_runtime.h>

// ---------------------------------------------------------------------------
// C3 sparsely-connected 5x5 conv, fp32, FFMA2 (fma.rn.f32x2) path, sm_103a.
// x: [32,6,512,512], w: [16,6,5,5], bias: [16] -> out: [32,16,508,508]
//
// R11 = R8 (best: 632us) + fully unrolled ky loop for cross-iteration
// load/FMA overlap (R8 exposed ~30 cyc of LDS latency per (ci,ky) iter).
//  - 3 CTAs/SM (launch_bounds(256,3)), 64x8 tile, 4 px x 8 co per thread.
//  - Dual smem input copies (aligned + shifted 1 float): all FFMA2 operands
//    come straight from LDS.128/LDS.64 — zero register packing in hot loop.
//  - Weights as (w,w) pairs in padded 6-pair rows: 3 broadcast loads per
//    (co,ci,ky), clean per-channel dependency chains (R10's streams hurt).
// ---------------------------------------------------------------------------

#define IN_H 512
#define IN_W 512
#define OUT_H 508
#define OUT_W 508
#define N_CI 6
#define N_CO 16

#define TILE_W 64
#define TILE_H 8
#define IN_TH 12          // TILE_H + 4
#define SA_STRIDE 68      // row stride in floats (272B, 16B-aligned rows)
#define CI_TILE (IN_TH * SA_STRIDE)   // 816 floats per channel plane
#define NTHREADS 256

// weights: rows of 6 pairs (kx 0..4 + pad), 16B aligned
#define SW_PAIRS (N_CO * N_CI * 5 * 6)           // 2880
#define SW_BYTES (SW_PAIRS * 8)                  // 23040
#define SA_BYTES (N_CI * CI_TILE * 4)            // 19584
#define SMEM_BYTES (SW_BYTES + 2 * SA_BYTES)     // 62208

typedef unsigned long long u64;

// Balanced co partition: 30 connected (co,ci) pairs per half.
__device__ constexpr int H_CO[2][8] = {
    {0, 1, 2, 3, 6, 7, 8, 15},
    {4, 5, 9, 10, 11, 12, 13, 14},
};
__device__ constexpr int HCNT[2][6] = { {3, 5, 7, 7, 5, 3}, {7, 5, 3, 3, 5, 7} };
__device__ constexpr int HLST[2][6][7] = {
  { // half 0
    {0, 4, 7, 0, 0, 0, 0},
    {0, 1, 4, 5, 7, 0, 0},
    {0, 1, 2, 4, 5, 6, 7},
    {1, 2, 3, 4, 5, 6, 7},
    {2, 3, 5, 6, 7, 0, 0},
    {3, 6, 7, 0, 0, 0, 0},
  },
  { // half 1
    {0, 1, 2, 3, 4, 5, 7},
    {1, 3, 4, 5, 6, 0, 0},
    {4, 6, 7, 0, 0, 0, 0},
    {2, 5, 7, 0, 0, 0, 0},
    {0, 2, 3, 5, 6, 0, 0},
    {0, 1, 2, 3, 4, 6, 7},
  },
};

__device__ __forceinline__ u64 pk2(float lo, float hi) {
    u64 r;
    asm("mov.b64 %0, {%1, %2};" : "=l"(r) : "f"(lo), "f"(hi));
    return r;
}

__device__ __forceinline__ void fma2(u64& d, u64 a, u64 b) {
    asm("fma.rn.f32x2 %0, %1, %2, %0;" : "+l"(d) : "l"(a), "l"(b));
}

__device__ __forceinline__ float2 upk(u64 v) {
    float2 r;
    asm("mov.b64 {%0, %1}, %2;" : "=f"(r.x), "=f"(r.y) : "l"(v));
    return r;
}

template <int H>
__device__ __forceinline__ void compute_half(
    const float* __restrict__ sA, const float* __restrict__ sB,
    const u64* __restrict__ sW, const float* __restrict__ bias,
    float* __restrict__ out, int b, int x0, int y0, int txi, int row)
{
    // 8 channels x 2 packed pairs (4 px), init with bias
    u64 acc[8][2];
#pragma unroll
    for (int a = 0; a < 8; ++a) {
        float bv = __ldg(bias + H_CO[H][a]);
        u64 bb = pk2(bv, bv);
        acc[a][0] = bb; acc[a][1] = bb;
    }

#pragma unroll
    for (int ci = 0; ci < N_CI; ++ci) {
        const float* bA = sA + ci * CI_TILE + row * SA_STRIDE + txi;
        const float* bB = sB + ci * CI_TILE + row * SA_STRIDE + txi;
#pragma unroll
        for (int ky = 0; ky < 5; ++ky) {
            // input pairs straight from LDS — issued first so ptxas can
            // overlap them with the previous iteration's FMA stream.
            ulonglong2 e0 = *reinterpret_cast<const ulonglong2*>(bA + ky * SA_STRIDE);
            ulonglong2 e1 = *reinterpret_cast<const ulonglong2*>(bA + ky * SA_STRIDE + 4);
            ulonglong2 o0 = *reinterpret_cast<const ulonglong2*>(bB + ky * SA_STRIDE);
            u64        o2 = *reinterpret_cast<const u64*>(bB + ky * SA_STRIDE + 4);
            u64 pe[4] = {e0.x, e0.y, e1.x, e1.y};   // pairs j = 0,2,4,6
            u64 po[3] = {o0.x, o0.y, o2};           // pairs j = 1,3,5

#pragma unroll
            for (int t = 0; t < HCNT[H][ci]; ++t) {
                const int a  = HLST[H][ci][t];
                const int co = H_CO[H][a];
                const u64* wr = sW + ((co * N_CI + ci) * 5 + ky) * 6;
                ulonglong2 w01 = *reinterpret_cast<const ulonglong2*>(wr);
                ulonglong2 w23 = *reinterpret_cast<const ulonglong2*>(wr + 2);
                u64        w4  = wr[4];
                // kx=0: j=0, j=2
                fma2(acc[a][0], pe[0], w01.x);
                fma2(acc[a][1], pe[1], w01.x);
                // kx=1: j=1, j=3
                fma2(acc[a][0], po[0], w01.y);
                fma2(acc[a][1], po[1], w01.y);
                // kx=2: j=2, j=4
                fma2(acc[a][0], pe[1], w23.x);
                fma2(acc[a][1], pe[2], w23.x);
                // kx=3: j=3, j=5
                fma2(acc[a][0], po[1], w23.y);
                fma2(acc[a][1], po[2], w23.y);
                // kx=4: j=4, j=6
                fma2(acc[a][0], pe[2], w4);
                fma2(acc[a][1], pe[3], w4);
            }
        }
    }

    // store: one float4 per channel (4 px, 16B aligned)
    const int ox = x0 + txi;
    const int oy = y0 + row;
    if (ox < OUT_W && oy < OUT_H) {
        float* ob = out + (size_t)b * (N_CO * OUT_H * OUT_W)
                        + (size_t)oy * OUT_W + ox;
#pragma unroll
        for (int a = 0; a < 8; ++a) {
            float2 v0 = upk(acc[a][0]);
            float2 v1 = upk(acc[a][1]);
            *reinterpret_cast<float4*>(ob + (size_t)H_CO[H][a] * (OUT_H * OUT_W)) =
                make_float4(v0.x, v0.y, v1.x, v1.y);
        }
    }
}

__global__ __launch_bounds__(NTHREADS, 3)
void c3_kernel(const float* __restrict__ x,
               const float* __restrict__ w,
               const float* __restrict__ bias,
               float* __restrict__ out) {
    extern __shared__ unsigned char smem[];
    u64*   sW = reinterpret_cast<u64*>(smem);
    float* sA = reinterpret_cast<float*>(smem + SW_BYTES);
    float* sB = reinterpret_cast<float*>(smem + SW_BYTES + SA_BYTES);

    const int tid = threadIdx.x;
    const int b   = blockIdx.z;
    const int x0  = blockIdx.x * TILE_W;
    const int y0  = blockIdx.y * TILE_H;

    // --- stage weights as (w,w) pairs, rows padded to 6 (48B, 16B-aligned) --
    for (int i = tid; i < N_CO * N_CI * 25; i += NTHREADS) {
        int co = i / 150;
        int r1 = i - co * 150;          // ci*25 + ky*5 + kx
        int ci = r1 / 25;
        int r2 = r1 - ci * 25;
        int ky = r2 / 5;
        int kx = r2 - ky * 5;
        float wv = w[i];
        sW[((co * N_CI + ci) * 5 + ky) * 6 + kx] = pk2(wv, wv);
    }

    // --- stage input tile into BOTH copies (aligned + shifted by 1 float) --
    const float* xb = x + (size_t)b * (N_CI * IN_H * IN_W);
    for (int i = tid; i < N_CI * IN_TH * 17; i += NTHREADS) {
        int ci  = i / (IN_TH * 17);
        int rem = i - ci * (IN_TH * 17);
        int r   = rem / 17;
        int c4  = (rem - r * 17) * 4;
        int gy  = y0 + r;
        int gx  = x0 + c4;
        float4 v = make_float4(0.f, 0.f, 0.f, 0.f);
        if (gy < IN_H && gx < IN_W) {
            v = *reinterpret_cast<const float4*>(
                    xb + (size_t)ci * (IN_H * IN_W) + (size_t)gy * IN_W + gx);
        }
        float* dA = sA + ci * CI_TILE + r * SA_STRIDE + c4;
        *reinterpret_cast<float4*>(dA) = v;
        // shifted copy: B[c] = in[c+1]
        float* dB = sB + ci * CI_TILE + r * SA_STRIDE + c4;
        if (c4 > 0) dB[-1] = v.x;
        dB[0] = v.y; dB[1] = v.z; dB[2] = v.w;
    }
    __syncthreads();

    const int xg   = tid & 15;         // 16 x-groups of 4 px
    const int row  = (tid >> 4) & 7;   // 8 rows
    const int half = tid >> 7;         // channel half (uniform per warp)
    const int txi  = xg * 4;

    if (half == 0)
        compute_half<0>(sA, sB, sW, bias, out, b, x0, y0, txi, row);
    else
        compute_half<1>(sA, sB, sW, bias, out, b, x0, y0, txi, row);
}

extern "C" void kernel_launch(void* const* d_in, const int* in_sizes, int n_in,
                              void* d_out, int out_size) {
    const float* x    = (const float*)d_in[0];   // [32,6,512,512]
    const float* w    = (const float*)d_in[1];   // [16,6,5,5]
    const float* bias = (const float*)d_in[2];   // [16]
    float* out = (float*)d_out;                  // [32,16,508,508]

    cudaFuncSetAttribute(c3_kernel,
                         cudaFuncAttributeMaxDynamicSharedMemorySize,
                         SMEM_BYTES);

    dim3 grid((OUT_W + TILE_W - 1) / TILE_W,    // 8
              (OUT_H + TILE_H - 1) / TILE_H,    // 64
              32);                              // batch
    c3_kernel<<<grid, NTHREADS, SMEM_BYTES>>>(x, w, bias, out);
}